// round 17
// baseline (speedup 1.0000x reference)
#include <cuda_runtime.h>
#include <cstdint>

// Inverted index scratch. g_head[row]: 0 = empty, else eid+1.
// g_next[eid]: 0 = end, else next_eid+1.  eid = b*Kp1 + k == output offset.
// g_head is zero at module load; the fused kernel's epilogue resets heads.
#define MAX_N (1 << 20)
#define MAX_E (1 << 21)
__device__ int g_head[MAX_N];
__device__ int g_next[MAX_E];

__device__ __forceinline__ uint32_t smem_u32(const void* p) {
    return (uint32_t)__cvta_generic_to_shared(p);
}

// ----------------------------------------------------------------------------
// Kernel B: bin score entries into per-row chains (scalar, serial — proven).
// ----------------------------------------------------------------------------
__global__ void bin_kernel(const int* __restrict__ idx, int E) {
    int eid = blockIdx.x * blockDim.x + threadIdx.x;
    if (eid >= E) return;
    int row = idx[eid];
    g_next[eid] = atomicExch(&g_head[row], eid + 1);
}

// ----------------------------------------------------------------------------
// Kernel C (TMA): fused copy + scores + positive momentum update.
// Block = 64-row tile (32 KB). The COPY is done by the TMA engine:
//   bulk load gmem->smem (mbarrier) ; bulk store smem->gmem (bulk_group).
// Warps only do chain work (rows read from smem), so chain stalls never
// gate copy bytes. Momentum rows are overwritten with STG after
// wait_group 0 + __syncthreads orders them against the bulk store.
// ----------------------------------------------------------------------------
#define TILE_ROWS 64
#define TILE_BYTES (TILE_ROWS * 512)     // 32 KB

template <int KP1C>
__global__ void __launch_bounds__(256)
fused_tma_kernel(const char* __restrict__ srcg,
                 char* __restrict__ dstg,
                 const float4* __restrict__ x4,
                 float* __restrict__ out,
                 int Kp1_rt, float invT) {
    const int Kp1 = (KP1C > 0) ? KP1C : Kp1_rt;
    const int tid = threadIdx.x;
    const int lane = tid & 31;
    const int wid = tid >> 5;                     // 0..7
    const int row0 = blockIdx.x * TILE_ROWS;
    const size_t base = (size_t)blockIdx.x * TILE_BYTES;

    __shared__ __align__(128) char buf[TILE_BYTES];
    __shared__ __align__(8) unsigned long long mbar;
    __shared__ int s_posb[8][8];

    const uint32_t mb   = smem_u32(&mbar);
    const uint32_t bufa = smem_u32(buf);

    if (tid == 0) {
        asm volatile("mbarrier.init.shared.b64 [%0], %1;"
                     :: "r"(mb), "r"(1) : "memory");
    }
    __syncthreads();

    if (tid == 0) {
        asm volatile("mbarrier.arrive.expect_tx.shared.b64 _, [%0], %1;"
                     :: "r"(mb), "r"((uint32_t)TILE_BYTES) : "memory");
        asm volatile(
            "cp.async.bulk.shared::cta.global.mbarrier::complete_tx::bytes "
            "[%0], [%1], %2, [%3];"
            :: "r"(bufa), "l"(srcg + base), "r"((uint32_t)TILE_BYTES), "r"(mb)
            : "memory");
    }

    // ---- wait for the tile (parity 0) ----
    {
        uint32_t done;
        asm volatile(
            "{\n\t.reg .pred p;\n\t"
            "mbarrier.try_wait.parity.acquire.cta.shared::cta.b64 p, [%1], %2;\n\t"
            "selp.b32 %0, 1, 0, p;\n\t}"
            : "=r"(done) : "r"(mb), "r"(0u) : "memory");
        if (!done) {
            asm volatile(
                "{\n\t.reg .pred P1;\n\t"
                "WAIT_%=:\n\t"
                "mbarrier.try_wait.parity.acquire.cta.shared::cta.b64 P1, [%0], %1, 0x989680;\n\t"
                "@P1 bra.uni DONE_%=;\n\t"
                "bra.uni WAIT_%=;\n\t"
                "DONE_%=:\n\t}"
                :: "r"(mb), "r"(0u) : "memory");
        }
    }

    // ---- issue the COPY: bulk store smem -> gmem (async in TMA engine) ----
    if (tid == 0) {
        asm volatile(
            "cp.async.bulk.global.shared::cta.bulk_group [%0], [%1], %2;"
            :: "l"(dstg + base), "r"(bufa), "r"((uint32_t)TILE_BYTES)
            : "memory");
        asm volatile("cp.async.bulk.commit_group;" ::: "memory");
    }

    // ---- chain work: warp wid owns rows row0 + wid*8 .. +7 ----
    const float4* rowbase =
        (const float4*)buf + (size_t)(wid * 8) * 32 + lane;

    #pragma unroll 1
    for (int j = 0; j < 8; j++) {
        int r = row0 + wid * 8 + j;
        int ee = g_head[r];                      // warp-uniform broadcast
        int posb = -1;
        if (ee != 0) {
            float4 rv = rowbase[j * 32];         // conflict-free LDS.128
            while (ee > 0) {
                int eid = ee - 1;
                unsigned int b = (unsigned int)eid / (unsigned int)Kp1;
                int k = eid - (int)b * Kp1;
                float4 xv = x4[b * 32 + lane];   // L1/L2-resident
                float s = rv.x * xv.x + rv.y * xv.y
                        + rv.z * xv.z + rv.w * xv.w;
                #pragma unroll
                for (int o = 16; o > 0; o >>= 1)
                    s += __shfl_xor_sync(0xffffffffu, s, o);
                if (lane == 0) out[eid] = s * invT;
                if (k == 0) posb = max(posb, (int)b);
                ee = g_next[eid];
            }
        }
        if (lane == 0) s_posb[wid][j] = posb;
    }

    // ---- order momentum STGs after the bulk store completes ----
    if (tid == 0) {
        asm volatile("cp.async.bulk.wait_group 0;" ::: "memory");
    }
    __syncthreads();

    // ---- momentum overwrites (~256 rows grid-wide) + head reset ----
    #pragma unroll 1
    for (int j = 0; j < 8; j++) {
        int posb = s_posb[wid][j];
        if (posb >= 0) {
            int r = row0 + wid * 8 + j;
            float4 rv = rowbase[j * 32];
            float4 xv = x4[posb * 32 + lane];
            float4 w;
            w.x = 0.5f * rv.x + 0.5f * xv.x;
            w.y = 0.5f * rv.y + 0.5f * xv.y;
            w.z = 0.5f * rv.z + 0.5f * xv.z;
            w.w = 0.5f * rv.w + 0.5f * xv.w;
            float ss = w.x * w.x + w.y * w.y + w.z * w.z + w.w * w.w;
            #pragma unroll
            for (int o = 16; o > 0; o >>= 1)
                ss += __shfl_xor_sync(0xffffffffu, ss, o);
            float inv = 1.0f / sqrtf(ss);
            w.x *= inv; w.y *= inv; w.z *= inv; w.w *= inv;
            *(float4*)(dstg + (size_t)r * 512 + lane * 16) = w;
        }
    }
    if (lane < 8) g_head[row0 + wid * 8 + lane] = 0;
}

// ----------------------------------------------------------------------------
// Fallback (non-exact shapes): proven R15 LDG kernel, RPW=2.
// ----------------------------------------------------------------------------
__device__ __forceinline__ float4 lds_f4_fresh(const float4* p) {
    float4 r;
    unsigned saddr = (unsigned)__cvta_generic_to_shared(p);
    asm volatile("ld.shared.v4.f32 {%0,%1,%2,%3}, [%4];"
                 : "=f"(r.x), "=f"(r.y), "=f"(r.z), "=f"(r.w)
                 : "r"(saddr));
    return r;
}

__global__ void __launch_bounds__(256, 8)
fused_ldg_kernel(const float4* __restrict__ mem4,
                 float4* __restrict__ dst4,
                 const float4* __restrict__ x4,
                 float* __restrict__ out,
                 int N, int Kp1, float invT) {
    const int lane = threadIdx.x & 31;
    const int wlocal = threadIdx.x >> 5;
    const int wg = (blockIdx.x * blockDim.x + threadIdx.x) >> 5;
    const int r0 = wg * 2;
    if (r0 >= N) return;

    __shared__ float4 stash[8 * 2 * 32];
    float4* my = &stash[wlocal * 64 + lane];

    const float4* src = mem4 + (size_t)r0 * 32 + lane;
    float4*       dst = dst4 + (size_t)r0 * 32 + lane;

    int hd[2];
    {
        float4 v[2];
        #pragma unroll
        for (int j = 0; j < 2; j++)
            if (r0 + j < N) v[j] = src[j * 32];
        #pragma unroll
        for (int j = 0; j < 2; j++)
            hd[j] = (r0 + j < N) ? g_head[r0 + j] : 0;
        #pragma unroll
        for (int j = 0; j < 2; j++)
            if (r0 + j < N) dst[j * 32] = v[j];
        #pragma unroll
        for (int j = 0; j < 2; j++)
            my[j * 32] = v[j];
    }
    if ((hd[0] | hd[1]) == 0) return;

    #pragma unroll
    for (int j = 0; j < 2; j++) {
        int ee = hd[j];
        int posb = -1;
        while (ee > 0) {
            int eid = ee - 1;
            unsigned int b = (unsigned int)eid / (unsigned int)Kp1;
            int k = eid - (int)b * Kp1;
            float4 xv = x4[b * 32 + lane];
            float4 rv = lds_f4_fresh(my + j * 32);
            float s = rv.x * xv.x + rv.y * xv.y + rv.z * xv.z + rv.w * xv.w;
            #pragma unroll
            for (int o = 16; o > 0; o >>= 1)
                s += __shfl_xor_sync(0xffffffffu, s, o);
            if (lane == 0) out[eid] = s * invT;
            if (k == 0) posb = max(posb, (int)b);
            ee = g_next[eid];
        }
        if (posb >= 0) {
            float4 xv = x4[posb * 32 + lane];
            float4 rv = lds_f4_fresh(my + j * 32);
            float4 w;
            w.x = 0.5f * rv.x + 0.5f * xv.x;
            w.y = 0.5f * rv.y + 0.5f * xv.y;
            w.z = 0.5f * rv.z + 0.5f * xv.z;
            w.w = 0.5f * rv.w + 0.5f * xv.w;
            float ss = w.x * w.x + w.y * w.y + w.z * w.z + w.w * w.w;
            #pragma unroll
            for (int o = 16; o > 0; o >>= 1)
                ss += __shfl_xor_sync(0xffffffffu, ss, o);
            float inv = 1.0f / sqrtf(ss);
            w.x *= inv; w.y *= inv; w.z *= inv; w.w *= inv;
            dst[j * 32] = w;
        }
    }
    if (lane < 2 && r0 + lane < N) g_head[r0 + lane] = 0;
}

// ----------------------------------------------------------------------------
// Launch. Inputs: x [B,D] f32, memory [N,D] f32, y [B] i32, idx [B,K+1] i32.
// Output: out [B,K+1] f32 then new_memory [N,D] f32.
// ----------------------------------------------------------------------------
extern "C" void kernel_launch(void* const* d_in, const int* in_sizes, int n_in,
                              void* d_out, int out_size) {
    const float* x      = (const float*)d_in[0];
    const float* memory = (const float*)d_in[1];
    const int*   idx    = (const int*)d_in[3];

    int B   = in_sizes[2];                  // 256
    int D   = in_sizes[0] / B;              // 128
    int Kp1 = in_sizes[3] / B;              // 4097
    int N   = in_sizes[1] / D;              // 1,000,000
    int E   = in_sizes[3];                  // 1,048,832

    float* out_scores = (float*)d_out;
    float* new_memory = (float*)d_out + (long long)E;

    const float invT = 1.0f / 0.07f;

    // B) bin score entries by memory row (serial, before fused)
    bin_kernel<<<(E + 255) / 256, 256>>>(idx, E);

    // C) fused copy + scores + positive update
    if (D == 128 && (N % TILE_ROWS) == 0) {
        int blocks = N / TILE_ROWS;              // 15625
        if (Kp1 == 4097) {
            fused_tma_kernel<4097><<<blocks, 256>>>(
                (const char*)memory, (char*)new_memory,
                (const float4*)x, out_scores, Kp1, invT);
        } else {
            fused_tma_kernel<0><<<blocks, 256>>>(
                (const char*)memory, (char*)new_memory,
                (const float4*)x, out_scores, Kp1, invT);
        }
    } else {
        int rows_per_block = 16;
        int blocks = (N + rows_per_block - 1) / rows_per_block;
        fused_ldg_kernel<<<blocks, 256>>>(
            (const float4*)memory, (float4*)new_memory,
            (const float4*)x, out_scores, N, Kp1, invT);
    }
}